// round 15
// baseline (speedup 1.0000x reference)
#include <cuda_runtime.h>
#include <cuda_fp16.h>
#include <math.h>
#include <stdint.h>

#define MAXE 400000
#define MAXN 50000

// Scratch (device globals: the sanctioned alloc-free workaround)
__device__ __half g_Bt[64 * 1024];             // Wm2 transposed [n][k], fp16
__device__ __half g_B0t[64 * 16];              // Wm0 transposed [n][k], fp16
__device__ __half g_B1t[64 * 64];              // Wm1 transposed [n][k], fp16
__device__ __half g_Wh[(size_t)MAXE * 1024];   // 819 MB: per-edge W (PERMUTED layout)
__device__ float  g_h0[(size_t)MAXN * 32];
__device__ float  g_ha[(size_t)MAXN * 32];
__device__ float  g_hb[(size_t)MAXN * 32];
__device__ float  g_agg[(size_t)MAXN * 32];

// Permuted W layout: W'[e][h*32 + c*8 + nt*2 + b] = W_e[h][nt*8 + 2c + b]

__device__ __forceinline__ void ldsm_x4(unsigned& r0, unsigned& r1,
                                        unsigned& r2, unsigned& r3, unsigned addr) {
    asm volatile("ldmatrix.sync.aligned.m8n8.x4.shared.b16 {%0,%1,%2,%3}, [%4];"
                 : "=r"(r0), "=r"(r1), "=r"(r2), "=r"(r3) : "r"(addr));
}
__device__ __forceinline__ void cp_async16(unsigned saddr, const void* gptr) {
    asm volatile("cp.async.cg.shared.global [%0], [%1], 16;" :: "r"(saddr), "l"(gptr));
}
__device__ __forceinline__ void cp_commit() {
    asm volatile("cp.async.commit_group;");
}
__device__ __forceinline__ void cp_wait_all() {
    asm volatile("cp.async.wait_group 0;");
}

// ---------------------------------------------------------------------------
// init: h0 = [x, zeros], agg = 0, out = 0
// ---------------------------------------------------------------------------
__global__ void k_init(const float* __restrict__ x, int N,
                       float* __restrict__ out, int out_size) {
    int i = blockIdx.x * blockDim.x + threadIdx.x;
    if (i < out_size) out[i] = 0.0f;
    if (i < N * 32) {
        int n = i >> 5, o = i & 31;
        g_h0[i] = (o < 16) ? x[n * 16 + o] : 0.0f;
        g_agg[i] = 0.0f;
    }
}

// convB: g_Bt[n][k] = fp16(Wm2[k][n]); also Wm0/Wm1 transposes
__global__ void k_convB(const float* __restrict__ B,
                        const float* __restrict__ W0, const float* __restrict__ W1) {
    int i = blockIdx.x * blockDim.x + threadIdx.x;
    if (i < 64 * 1024) {
        int n = i >> 6, k = i & 63;
        g_Bt[i] = __float2half_rn(B[k * 1024 + n]);
    }
    if (i < 64 * 16) {
        int n = i >> 4, k = i & 15;
        g_B0t[i] = __float2half_rn(W0[k * 64 + n]);
    }
    if (i < 64 * 64) {
        int n = i >> 6, k = i & 63;
        g_B1t[i] = __float2half_rn(W1[k * 64 + n]);
    }
}

// ---------------------------------------------------------------------------
// FUSED edge MLP + W GEMM.
// Phase 1 (MLP): e2 = relu(relu(ea@Wm0+bm0)@Wm1+bm1) -> sA (fp16, pitch 72)
// Phase 2 (GEMM): permuted W from sA @ Wm2 + bm2, double-buffered cp.async B.
// MLP temporaries alias the B double-buffer (barrier-ordered).
// ---------------------------------------------------------------------------
#define EP 24
#define HP 72
#define HPITCH 72

__global__ __launch_bounds__(256) void k_fused(
    const float* __restrict__ ea,
    const float* __restrict__ bm0, const float* __restrict__ bm1,
    const float* __restrict__ bias, int E) {
    __shared__ __half sA[128 * HPITCH];   // h1 -> e2 -> GEMM A   (18,432 B)
    __shared__ __half sU[2 * 64 * HPITCH];// MLP temps / B dbl buf (18,432 B)
    __shared__ float  sbias[512];
    __shared__ float  sb0[64], sb1[64];

    // MLP temp aliases inside sU (half indices):
    //   sEA = sU[0 .. 3071]      (128 x EP)   } = buf0 region [0..4607]
    //   sB0 = sU[3072 .. 4607]   (64 x EP)    }
    //   sB1 = sU[4608 .. 9215]   (64 x HP)    = buf1 region
    __half* sEA = sU;
    __half* sB0 = sU + 128 * EP;
    __half* sB1 = sU + 64 * HPITCH;

    int tid = threadIdx.x;
    int bm = blockIdx.x * 128;
    int bn0 = blockIdx.y * 512;
    int r = tid >> 3;
    int x = tid & 7;

    if (tid < 64) sb0[tid] = bm0[tid];
    else if (tid < 128) sb1[tid - 64] = bm1[tid - 64];
    sbias[tid] = bias[bn0 + tid];
    sbias[tid + 256] = bias[bn0 + tid + 256];

    // stage sEA: thread t -> edge t/2, feature-half t&1
    {
        int el = tid >> 1, p = tid & 1;
        int rr = bm + el; if (rr >= E) rr = E - 1;
        const float4* src = (const float4*)(ea + (size_t)rr * 16 + p * 8);
        float4 v0 = src[0], v1 = src[1];
        __half2 h0 = __floats2half2_rn(v0.x, v0.y);
        __half2 h1_ = __floats2half2_rn(v0.z, v0.w);
        __half2 h2 = __floats2half2_rn(v1.x, v1.y);
        __half2 h3 = __floats2half2_rn(v1.z, v1.w);
        uint4 pk;
        pk.x = *(unsigned*)&h0; pk.y = *(unsigned*)&h1_;
        pk.z = *(unsigned*)&h2; pk.w = *(unsigned*)&h3;
        *(uint4*)&sEA[el * EP + p * 8] = pk;
    }
    if (tid < 128) {
        int row = tid >> 1, xx = tid & 1;
        uint4 v = *(const uint4*)(g_B0t + row * 16 + xx * 8);
        *(uint4*)&sB0[row * EP + xx * 8] = v;
    }
    {
#pragma unroll
        for (int i = 0; i < 2; i++) {
            int row = (tid >> 3) + i * 32;
            uint4 v = *(const uint4*)(g_B1t + (size_t)row * 64 + x * 8);
            *(uint4*)&sB1[row * HP + x * 8] = v;
        }
    }
    __syncthreads();

    int lane = tid & 31;
    int warp = tid >> 5;
    int wm = warp & 3;
    int wn = warp >> 2;
    int g = lane >> 2;
    int c = lane & 3;

    // ---- MLP layer 1: [128,16] @ [16,64] -> h1 in sA ----
    float acc[2][4][4];
#pragma unroll
    for (int mt = 0; mt < 2; mt++)
#pragma unroll
        for (int nt = 0; nt < 4; nt++)
#pragma unroll
            for (int q = 0; q < 4; q++) acc[mt][nt][q] = 0.f;
    {
        unsigned a_[2][4];
#pragma unroll
        for (int mt = 0; mt < 2; mt++) {
            int r0 = wm * 32 + mt * 16 + g;
            a_[mt][0] = *(const unsigned*)&sEA[r0 * EP + 2 * c];
            a_[mt][1] = *(const unsigned*)&sEA[(r0 + 8) * EP + 2 * c];
            a_[mt][2] = *(const unsigned*)&sEA[r0 * EP + 2 * c + 8];
            a_[mt][3] = *(const unsigned*)&sEA[(r0 + 8) * EP + 2 * c + 8];
        }
#pragma unroll
        for (int nt = 0; nt < 4; nt++) {
            int n0 = wn * 32 + nt * 8 + g;
            unsigned b0 = *(const unsigned*)&sB0[n0 * EP + 2 * c];
            unsigned b1 = *(const unsigned*)&sB0[n0 * EP + 2 * c + 8];
#pragma unroll
            for (int mt = 0; mt < 2; mt++) {
                asm volatile(
                    "mma.sync.aligned.m16n8k16.row.col.f32.f16.f16.f32 "
                    "{%0,%1,%2,%3}, {%4,%5,%6,%7}, {%8,%9}, {%0,%1,%2,%3};"
                    : "+f"(acc[mt][nt][0]), "+f"(acc[mt][nt][1]),
                      "+f"(acc[mt][nt][2]), "+f"(acc[mt][nt][3])
                    : "r"(a_[mt][0]), "r"(a_[mt][1]), "r"(a_[mt][2]), "r"(a_[mt][3]),
                      "r"(b0), "r"(b1));
            }
        }
    }
#pragma unroll
    for (int nt = 0; nt < 4; nt++) {
        int col = wn * 32 + nt * 8 + 2 * c;
        float bx = sb0[col], by = sb0[col + 1];
#pragma unroll
        for (int mt = 0; mt < 2; mt++) {
            int r0 = wm * 32 + mt * 16 + g;
            __half2 v0 = __floats2half2_rn(fmaxf(acc[mt][nt][0] + bx, 0.f),
                                           fmaxf(acc[mt][nt][1] + by, 0.f));
            *(__half2*)&sA[r0 * HP + col] = v0;
            __half2 v1 = __floats2half2_rn(fmaxf(acc[mt][nt][2] + bx, 0.f),
                                           fmaxf(acc[mt][nt][3] + by, 0.f));
            *(__half2*)&sA[(r0 + 8) * HP + col] = v1;
        }
    }
    __syncthreads();   // layer-1 reads of sEA/sB0 (buf0) done; h1 visible

    // prefetch B chunk 0 into buf0 (overlaps layer 2)
#pragma unroll
    for (int i = 0; i < 2; i++) {
        int row = r + i * 32;
        unsigned sa = (unsigned)__cvta_generic_to_shared((char*)sU + row * 144 + x * 16);
        cp_async16(sa, g_Bt + (size_t)(bn0 + row) * 64 + x * 8);
    }
    cp_commit();

    // ---- MLP layer 2: [128,64] @ [64,64], A = h1 in sA, B = sB1 (buf1) ----
#pragma unroll
    for (int mt = 0; mt < 2; mt++)
#pragma unroll
        for (int nt = 0; nt < 4; nt++)
#pragma unroll
            for (int q = 0; q < 4; q++) acc[mt][nt][q] = 0.f;

#pragma unroll
    for (int kk = 0; kk < 4; kk++) {
        int kb = kk * 16;
        unsigned a_[2][4];
#pragma unroll
        for (int mt = 0; mt < 2; mt++) {
            int r0 = wm * 32 + mt * 16 + g;
            a_[mt][0] = *(const unsigned*)&sA[r0 * HP + kb + 2 * c];
            a_[mt][1] = *(const unsigned*)&sA[(r0 + 8) * HP + kb + 2 * c];
            a_[mt][2] = *(const unsigned*)&sA[r0 * HP + kb + 2 * c + 8];
            a_[mt][3] = *(const unsigned*)&sA[(r0 + 8) * HP + kb + 2 * c + 8];
        }
#pragma unroll
        for (int nt = 0; nt < 4; nt++) {
            int n0 = wn * 32 + nt * 8 + g;
            unsigned b0 = *(const unsigned*)&sB1[n0 * HP + kb + 2 * c];
            unsigned b1 = *(const unsigned*)&sB1[n0 * HP + kb + 2 * c + 8];
#pragma unroll
            for (int mt = 0; mt < 2; mt++) {
                asm volatile(
                    "mma.sync.aligned.m16n8k16.row.col.f32.f16.f16.f32 "
                    "{%0,%1,%2,%3}, {%4,%5,%6,%7}, {%8,%9}, {%0,%1,%2,%3};"
                    : "+f"(acc[mt][nt][0]), "+f"(acc[mt][nt][1]),
                      "+f"(acc[mt][nt][2]), "+f"(acc[mt][nt][3])
                    : "r"(a_[mt][0]), "r"(a_[mt][1]), "r"(a_[mt][2]), "r"(a_[mt][3]),
                      "r"(b0), "r"(b1));
            }
        }
    }
    __syncthreads();   // all sA (h1) + sB1 (buf1) reads done

    // epilogue: e2 = bias + relu -> sA (GEMM A tile)
#pragma unroll
    for (int nt = 0; nt < 4; nt++) {
        int col = wn * 32 + nt * 8 + 2 * c;
        float bx = sb1[col], by = sb1[col + 1];
#pragma unroll
        for (int mt = 0; mt < 2; mt++) {
            int r0 = wm * 32 + mt * 16 + g;
            __half2 v0 = __floats2half2_rn(fmaxf(acc[mt][nt][0] + bx, 0.f),
                                           fmaxf(acc[mt][nt][1] + by, 0.f));
            *(__half2*)&sA[r0 * HP + col] = v0;
            __half2 v1 = __floats2half2_rn(fmaxf(acc[mt][nt][2] + bx, 0.f),
                                           fmaxf(acc[mt][nt][3] + by, 0.f));
            *(__half2*)&sA[(r0 + 8) * HP + col] = v1;
        }
    }

    // ---- GEMM phase ----
    int sel = lane >> 3;
    int l7 = lane & 7;

    unsigned aAddr[4][2];
#pragma unroll
    for (int kk = 0; kk < 4; kk++) {
#pragma unroll
        for (int mt = 0; mt < 2; mt++) {
            int rowa = wm * 32 + mt * 16 + (sel & 1) * 8 + l7;
            int cola = kk * 16 + (sel >> 1) * 8;
            aAddr[kk][mt] = (unsigned)__cvta_generic_to_shared(&sA[rowa * HPITCH + cola]);
        }
    }

#pragma unroll 1
    for (int ch = 0; ch < 8; ch++) {
        cp_wait_all();
        __syncthreads();   // B[ch&1] ready; e2 visible (ch=0); prev iter done

        if (ch < 7) {
            int bnn = bn0 + (ch + 1) * 64;
            char* dstbuf = (char*)sU + ((ch + 1) & 1) * (64 * 144);
#pragma unroll
            for (int i = 0; i < 2; i++) {
                int row = r + i * 32;
                unsigned sa = (unsigned)__cvta_generic_to_shared(dstbuf + row * 144 + x * 16);
                cp_async16(sa, g_Bt + (size_t)(bnn + row) * 64 + x * 8);
            }
        }
        cp_commit();

        const __half* sBc = sU + (ch & 1) * (64 * HPITCH);
        int bn = bn0 + ch * 64;

        float acc2[2][4][4];
#pragma unroll
        for (int mt = 0; mt < 2; mt++)
#pragma unroll
            for (int nt = 0; nt < 4; nt++)
#pragma unroll
                for (int q = 0; q < 4; q++) acc2[mt][nt][q] = 0.f;

#pragma unroll
        for (int kk = 0; kk < 4; kk++) {
            int kb = kk * 16;
            unsigned a_[2][4];
#pragma unroll
            for (int mt = 0; mt < 2; mt++)
                ldsm_x4(a_[mt][0], a_[mt][1], a_[mt][2], a_[mt][3], aAddr[kk][mt]);

            unsigned b_[4][2];
            {
                int rowb0 = wn * 32 + ((sel < 2) ? 0 : 8) + l7;
                int colb  = kb + (sel & 1) * 8;
                unsigned a0 = (unsigned)__cvta_generic_to_shared(&sBc[rowb0 * HPITCH + colb]);
                ldsm_x4(b_[0][0], b_[0][1], b_[1][0], b_[1][1], a0);
                int rowb1 = wn * 32 + ((sel < 2) ? 16 : 24) + l7;
                unsigned a1 = (unsigned)__cvta_generic_to_shared(&sBc[rowb1 * HPITCH + colb]);
                ldsm_x4(b_[2][0], b_[2][1], b_[3][0], b_[3][1], a1);
            }
#pragma unroll
            for (int mt = 0; mt < 2; mt++)
#pragma unroll
                for (int nt = 0; nt < 4; nt++) {
                    asm volatile(
                        "mma.sync.aligned.m16n8k16.row.col.f32.f16.f16.f32 "
                        "{%0,%1,%2,%3}, {%4,%5,%6,%7}, {%8,%9}, {%0,%1,%2,%3};"
                        : "+f"(acc2[mt][nt][0]), "+f"(acc2[mt][nt][1]),
                          "+f"(acc2[mt][nt][2]), "+f"(acc2[mt][nt][3])
                        : "r"(a_[mt][0]), "r"(a_[mt][1]), "r"(a_[mt][2]), "r"(a_[mt][3]),
                          "r"(b_[nt][0]), "r"(b_[nt][1]));
                }
        }

        // direct permuted store
        {
            int hcol = (bn + wn * 32);
            int cb = ch * 64 + wn * 32;
            float bb[4][2];
#pragma unroll
            for (int nt = 0; nt < 4; nt++) {
                int col = cb + nt * 8 + 2 * c;
                bb[nt][0] = sbias[col];
                bb[nt][1] = sbias[col + 1];
            }
#pragma unroll
            for (int mt = 0; mt < 2; mt++) {
#pragma unroll
                for (int q = 0; q < 2; q++) {
                    int er = bm + wm * 32 + mt * 16 + q * 8 + g;
                    if (er < E) {
                        __half2 v[4];
#pragma unroll
                        for (int nt = 0; nt < 4; nt++)
                            v[nt] = __floats2half2_rn(acc2[mt][nt][2 * q] + bb[nt][0],
                                                      acc2[mt][nt][2 * q + 1] + bb[nt][1]);
                        uint4 pk;
                        pk.x = *(unsigned*)&v[0]; pk.y = *(unsigned*)&v[1];
                        pk.z = *(unsigned*)&v[2]; pk.w = *(unsigned*)&v[3];
                        *(uint4*)(g_Wh + (size_t)er * 1024 + hcol + c * 8) = pk;
                    }
                }
            }
        }
    }
}

// ---------------------------------------------------------------------------
// message passing (unchanged)
// ---------------------------------------------------------------------------
__global__ __launch_bounds__(256) void k_msg(const int* __restrict__ ei, int selIn, int E) {
    int gw = (blockIdx.x * blockDim.x + threadIdx.x) >> 5;
    int lane = threadIdx.x & 31;
    if (gw >= E) return;
    const float* __restrict__ h = (selIn == 0) ? g_h0 : (selIn == 1) ? g_ha : g_hb;

    int2 sd = ((const int2*)ei)[gw];
    int src = sd.x, dst = sd.y;
    float hval = h[(size_t)src * 32 + lane];

    const uint4* __restrict__ W16 = (const uint4*)(g_Wh + (size_t)gw * 1024);
    float acc[8];
#pragma unroll
    for (int j = 0; j < 8; j++) acc[j] = 0.f;

#pragma unroll
    for (int i = 0; i < 4; i++) {
        uint4 w = W16[lane + 32 * i];
        float hs = __shfl_sync(0xffffffffu, hval, (lane >> 2) + 8 * i);
        const __half2* h2 = (const __half2*)&w;
#pragma unroll
        for (int j = 0; j < 4; j++) {
            float2 f = __half22float2(h2[j]);
            acc[2 * j]     += hs * f.x;
            acc[2 * j + 1] += hs * f.y;
        }
    }
#pragma unroll
    for (int m = 4; m <= 16; m <<= 1) {
#pragma unroll
        for (int j = 0; j < 8; j++)
            acc[j] += __shfl_xor_sync(0xffffffffu, acc[j], m);
    }
    int k = lane >> 2;
    float v = acc[0];
    if (k == 1) v = acc[1];
    if (k == 2) v = acc[2];
    if (k == 3) v = acc[3];
    if (k == 4) v = acc[4];
    if (k == 5) v = acc[5];
    if (k == 6) v = acc[6];
    if (k == 7) v = acc[7];
    int o = ((k >> 1) << 3) + ((lane & 3) << 1) + (k & 1);
    atomicAdd(&g_agg[(size_t)dst * 32 + o], v);
}

// ---------------------------------------------------------------------------
// node update (unchanged wide version)
// ---------------------------------------------------------------------------
__global__ __launch_bounds__(1024) void k_update(
    int selIn, int selOut, const float* __restrict__ root,
    const float* __restrict__ bias, int N) {
    __shared__ float sroot[32 * 32];
    __shared__ float sb[32];
    int tid = threadIdx.x;
    if (tid < 1024) sroot[tid] = root[tid];
    if (tid < 32) sb[tid] = bias[tid];
    __syncthreads();

    int lane = tid & 31, w = tid >> 5;
    int n = blockIdx.x * 32 + w;
    if (n >= N) return;
    const float* __restrict__ hin = (selIn == 0) ? g_h0 : (selIn == 1) ? g_ha : g_hb;
    float* __restrict__ hout = (selOut == 1) ? g_ha : g_hb;

    float hv = hin[(size_t)n * 32 + lane];
    float acc = sb[lane] + g_agg[(size_t)n * 32 + lane];
    g_agg[(size_t)n * 32 + lane] = 0.0f;
#pragma unroll
    for (int k = 0; k < 32; k++)
        acc += __shfl_sync(0xffffffffu, hv, k) * sroot[k * 32 + lane];
    hout[(size_t)n * 32 + lane] = acc;
}

// ---------------------------------------------------------------------------
// readout (unchanged wide version)
// ---------------------------------------------------------------------------
__global__ __launch_bounds__(1024) void k_readout(
    const float* __restrict__ Wi0, const float* __restrict__ bi0,
    const float* __restrict__ Wi1, const float* __restrict__ bi1,
    const float* __restrict__ Wj0, const float* __restrict__ bj0,
    const float* __restrict__ Wj1, const float* __restrict__ bj1,
    float* __restrict__ out, int N) {
    __shared__ float sW[64 * 128];
    __shared__ float sv1[128];
    __shared__ float sblock;
    int tid = threadIdx.x, lane = tid & 31, w = tid >> 5;
    int n = blockIdx.x * 32 + w;
    bool active = (n < N);

    for (int i = tid; i < 64 * 128; i += 1024) sW[i] = Wi0[i];
    if (tid < 128) sv1[tid] = Wi1[tid];
    if (tid == 0) sblock = 0.f;
    __syncthreads();

    float za = 0.f, zb = 0.f;
    if (active) {
        za = g_ha[(size_t)n * 32 + lane];
        zb = g_h0[(size_t)n * 32 + lane];
    }

    float a0 = bi0[lane], a1 = bi0[lane + 32], a2 = bi0[lane + 64], a3 = bi0[lane + 96];
#pragma unroll
    for (int k = 0; k < 32; k++) {
        float zk = __shfl_sync(0xffffffffu, za, k);
        a0 += zk * sW[k * 128 + lane];
        a1 += zk * sW[k * 128 + lane + 32];
        a2 += zk * sW[k * 128 + lane + 64];
        a3 += zk * sW[k * 128 + lane + 96];
    }
#pragma unroll
    for (int k = 0; k < 32; k++) {
        float zk = __shfl_sync(0xffffffffu, zb, k);
        a0 += zk * sW[(k + 32) * 128 + lane];
        a1 += zk * sW[(k + 32) * 128 + lane + 32];
        a2 += zk * sW[(k + 32) * 128 + lane + 64];
        a3 += zk * sW[(k + 32) * 128 + lane + 96];
    }
    a0 = fmaxf(a0, 0.f); a1 = fmaxf(a1, 0.f); a2 = fmaxf(a2, 0.f); a3 = fmaxf(a3, 0.f);
    float gp = a0 * sv1[lane] + a1 * sv1[lane + 32] + a2 * sv1[lane + 64] + a3 * sv1[lane + 96];
#pragma unroll
    for (int s = 16; s > 0; s >>= 1) gp += __shfl_xor_sync(0xffffffffu, gp, s);
    float gate = 1.0f / (1.0f + expf(-(gp + bi1[0])));

    __syncthreads();
    for (int i = tid; i < 32 * 128; i += 1024) sW[i] = Wj0[i];
    if (tid < 128) sv1[tid] = Wj1[tid];
    __syncthreads();

    float b0 = bj0[lane], b1 = bj0[lane + 32], b2 = bj0[lane + 64], b3 = bj0[lane + 96];
#pragma unroll
    for (int k = 0; k < 32; k++) {
        float zk = __shfl_sync(0xffffffffu, za, k);
        b0 += zk * sW[k * 128 + lane];
        b1 += zk * sW[k * 128 + lane + 32];
        b2 += zk * sW[k * 128 + lane + 64];
        b3 += zk * sW[k * 128 + lane + 96];
    }
    b0 = fmaxf(b0, 0.f); b1 = fmaxf(b1, 0.f); b2 = fmaxf(b2, 0.f); b3 = fmaxf(b3, 0.f);
    float vp = b0 * sv1[lane] + b1 * sv1[lane + 32] + b2 * sv1[lane + 64] + b3 * sv1[lane + 96];
#pragma unroll
    for (int s = 16; s > 0; s >>= 1) vp += __shfl_xor_sync(0xffffffffu, vp, s);
    float val = vp + bj1[0];

    if (active && lane == 0) atomicAdd(&sblock, gate * val);
    __syncthreads();
    if (tid == 0) atomicAdd(out, sblock);
}

// ---------------------------------------------------------------------------
extern "C" void kernel_launch(void* const* d_in, const int* in_sizes, int n_in,
                              void* d_out, int out_size) {
    const float* x   = (const float*)d_in[0];
    const int*   ei  = (const int*)d_in[1];
    const float* ea  = (const float*)d_in[2];
    const float* Wm0 = (const float*)d_in[3];  const float* bm0 = (const float*)d_in[4];
    const float* Wm1 = (const float*)d_in[5];  const float* bm1 = (const float*)d_in[6];
    const float* Wm2 = (const float*)d_in[7];  const float* bm2 = (const float*)d_in[8];
    const float* root= (const float*)d_in[9];  const float* bias= (const float*)d_in[10];
    const float* Wi0 = (const float*)d_in[11]; const float* bi0 = (const float*)d_in[12];
    const float* Wi1 = (const float*)d_in[13]; const float* bi1 = (const float*)d_in[14];
    const float* Wj0 = (const float*)d_in[15]; const float* bj0 = (const float*)d_in[16];
    const float* Wj1 = (const float*)d_in[17]; const float* bj1 = (const float*)d_in[18];
    int N = in_sizes[0] / 16;
    int E = in_sizes[2] / 16;
    float* out = (float*)d_out;

    k_init<<<(N * 32 + 255) / 256, 256>>>(x, N, out, out_size);
    k_convB<<<(64 * 1024 + 255) / 256, 256>>>(Wm2, Wm0, Wm1);

    dim3 gg((E + 127) / 128, 2);
    k_fused<<<gg, 256>>>(ea, bm0, bm1, bm2, E);

    int msgBlocks = (E + 7) / 8;
    int nodeBlocks = (N + 31) / 32;
    // iter 1: h0 -> ha
    k_msg<<<msgBlocks, 256>>>(ei, 0, E);
    k_update<<<nodeBlocks, 1024>>>(0, 1, root, bias, N);
    // iter 2: ha -> hb
    k_msg<<<msgBlocks, 256>>>(ei, 1, E);
    k_update<<<nodeBlocks, 1024>>>(1, 2, root, bias, N);
    // iter 3: hb -> ha
    k_msg<<<msgBlocks, 256>>>(ei, 2, E);
    k_update<<<nodeBlocks, 1024>>>(2, 1, root, bias, N);

    k_readout<<<nodeBlocks, 1024>>>(Wi0, bi0, Wi1, bi1, Wj0, bj0, Wj1, bj1, out, N);
}

// round 16
// speedup vs baseline: 1.0263x; 1.0263x over previous
#include <cuda_runtime.h>
#include <cuda_fp16.h>
#include <math.h>
#include <stdint.h>

#define MAXE 400000
#define MAXN 50000

// Scratch (device globals: the sanctioned alloc-free workaround)
__device__ __half g_Bt[64 * 1024];             // Wm2 transposed [n][k], fp16
__device__ __half g_B0t[64 * 16];              // Wm0 transposed [n][k], fp16
__device__ __half g_B1t[64 * 64];              // Wm1 transposed [n][k], fp16
__device__ __half g_Wh[(size_t)MAXE * 1024];   // 819 MB: per-edge W (PERMUTED layout)
__device__ float  g_h0[(size_t)MAXN * 32];
__device__ float  g_ha[(size_t)MAXN * 32];
__device__ float  g_hb[(size_t)MAXN * 32];
__device__ float  g_agg[(size_t)MAXN * 32];

// Permuted W layout: W'[e][h*32 + c*8 + nt*2 + b] = W_e[h][nt*8 + 2c + b]

__device__ __forceinline__ void ldsm_x4(unsigned& r0, unsigned& r1,
                                        unsigned& r2, unsigned& r3, unsigned addr) {
    asm volatile("ldmatrix.sync.aligned.m8n8.x4.shared.b16 {%0,%1,%2,%3}, [%4];"
                 : "=r"(r0), "=r"(r1), "=r"(r2), "=r"(r3) : "r"(addr));
}
__device__ __forceinline__ void cp_async16(unsigned saddr, const void* gptr) {
    asm volatile("cp.async.cg.shared.global [%0], [%1], 16;" :: "r"(saddr), "l"(gptr));
}
__device__ __forceinline__ void cp_commit() {
    asm volatile("cp.async.commit_group;");
}
__device__ __forceinline__ void cp_wait_all() {
    asm volatile("cp.async.wait_group 0;");
}

// ---------------------------------------------------------------------------
// init: h0 = [x, zeros], agg = 0, out = 0
// ---------------------------------------------------------------------------
__global__ void k_init(const float* __restrict__ x, int N,
                       float* __restrict__ out, int out_size) {
    int i = blockIdx.x * blockDim.x + threadIdx.x;
    if (i < out_size) out[i] = 0.0f;
    if (i < N * 32) {
        int n = i >> 5, o = i & 31;
        g_h0[i] = (o < 16) ? x[n * 16 + o] : 0.0f;
        g_agg[i] = 0.0f;
    }
}

// convB: g_Bt[n][k] = fp16(Wm2[k][n]); also Wm0/Wm1 transposes
__global__ void k_convB(const float* __restrict__ B,
                        const float* __restrict__ W0, const float* __restrict__ W1) {
    int i = blockIdx.x * blockDim.x + threadIdx.x;
    if (i < 64 * 1024) {
        int n = i >> 6, k = i & 63;
        g_Bt[i] = __float2half_rn(B[k * 1024 + n]);
    }
    if (i < 64 * 16) {
        int n = i >> 4, k = i & 15;
        g_B0t[i] = __float2half_rn(W0[k * 64 + n]);
    }
    if (i < 64 * 64) {
        int n = i >> 6, k = i & 63;
        g_B1t[i] = __float2half_rn(W1[k * 64 + n]);
    }
}

// ---------------------------------------------------------------------------
// FUSED edge MLP + W GEMM (grid.y = 1: MLP computed ONCE per edge tile).
// Phase 1 (MLP): e2 = relu(relu(ea@Wm0+bm0)@Wm1+bm1) -> sA (fp16, pitch 72)
// Phase 2 (GEMM): permuted W over ALL 1024 cols (16 chunks), dbl-buf cp.async.
// ---------------------------------------------------------------------------
#define EP 24
#define HP 72
#define HPITCH 72

__global__ __launch_bounds__(256) void k_fused(
    const float* __restrict__ ea,
    const float* __restrict__ bm0, const float* __restrict__ bm1,
    const float* __restrict__ bias, int E) {
    __shared__ __half sA[128 * HPITCH];    // h1 -> e2 -> GEMM A   (18,432 B)
    __shared__ __half sU[2 * 64 * HPITCH]; // MLP temps / B dbl buf (18,432 B)
    __shared__ float  sbias[1024];
    __shared__ float  sb0[64], sb1[64];

    __half* sEA = sU;                 // 128 x EP   } buf0 region
    __half* sB0 = sU + 128 * EP;      // 64 x EP    }
    __half* sB1 = sU + 64 * HPITCH;   // 64 x HP    = buf1 region

    int tid = threadIdx.x;
    int bm = blockIdx.x * 128;
    int r = tid >> 3;
    int x = tid & 7;

    if (tid < 64) sb0[tid] = bm0[tid];
    else if (tid < 128) sb1[tid - 64] = bm1[tid - 64];
#pragma unroll
    for (int i = 0; i < 4; i++) sbias[tid + i * 256] = bias[tid + i * 256];

    // stage sEA: thread t -> edge t/2, feature-half t&1
    {
        int el = tid >> 1, p = tid & 1;
        int rr = bm + el; if (rr >= E) rr = E - 1;
        const float4* src = (const float4*)(ea + (size_t)rr * 16 + p * 8);
        float4 v0 = src[0], v1 = src[1];
        __half2 h0 = __floats2half2_rn(v0.x, v0.y);
        __half2 h1_ = __floats2half2_rn(v0.z, v0.w);
        __half2 h2 = __floats2half2_rn(v1.x, v1.y);
        __half2 h3 = __floats2half2_rn(v1.z, v1.w);
        uint4 pk;
        pk.x = *(unsigned*)&h0; pk.y = *(unsigned*)&h1_;
        pk.z = *(unsigned*)&h2; pk.w = *(unsigned*)&h3;
        *(uint4*)&sEA[el * EP + p * 8] = pk;
    }
    if (tid < 128) {
        int row = tid >> 1, xx = tid & 1;
        uint4 v = *(const uint4*)(g_B0t + row * 16 + xx * 8);
        *(uint4*)&sB0[row * EP + xx * 8] = v;
    }
    {
#pragma unroll
        for (int i = 0; i < 2; i++) {
            int row = (tid >> 3) + i * 32;
            uint4 v = *(const uint4*)(g_B1t + (size_t)row * 64 + x * 8);
            *(uint4*)&sB1[row * HP + x * 8] = v;
        }
    }
    __syncthreads();

    int lane = tid & 31;
    int warp = tid >> 5;
    int wm = warp & 3;
    int wn = warp >> 2;
    int g = lane >> 2;
    int c = lane & 3;

    // ---- MLP layer 1: [128,16] @ [16,64] -> h1 in sA ----
    float acc[2][4][4];
#pragma unroll
    for (int mt = 0; mt < 2; mt++)
#pragma unroll
        for (int nt = 0; nt < 4; nt++)
#pragma unroll
            for (int q = 0; q < 4; q++) acc[mt][nt][q] = 0.f;
    {
        unsigned a_[2][4];
#pragma unroll
        for (int mt = 0; mt < 2; mt++) {
            int r0 = wm * 32 + mt * 16 + g;
            a_[mt][0] = *(const unsigned*)&sEA[r0 * EP + 2 * c];
            a_[mt][1] = *(const unsigned*)&sEA[(r0 + 8) * EP + 2 * c];
            a_[mt][2] = *(const unsigned*)&sEA[r0 * EP + 2 * c + 8];
            a_[mt][3] = *(const unsigned*)&sEA[(r0 + 8) * EP + 2 * c + 8];
        }
#pragma unroll
        for (int nt = 0; nt < 4; nt++) {
            int n0 = wn * 32 + nt * 8 + g;
            unsigned b0 = *(const unsigned*)&sB0[n0 * EP + 2 * c];
            unsigned b1 = *(const unsigned*)&sB0[n0 * EP + 2 * c + 8];
#pragma unroll
            for (int mt = 0; mt < 2; mt++) {
                asm volatile(
                    "mma.sync.aligned.m16n8k16.row.col.f32.f16.f16.f32 "
                    "{%0,%1,%2,%3}, {%4,%5,%6,%7}, {%8,%9}, {%0,%1,%2,%3};"
                    : "+f"(acc[mt][nt][0]), "+f"(acc[mt][nt][1]),
                      "+f"(acc[mt][nt][2]), "+f"(acc[mt][nt][3])
                    : "r"(a_[mt][0]), "r"(a_[mt][1]), "r"(a_[mt][2]), "r"(a_[mt][3]),
                      "r"(b0), "r"(b1));
            }
        }
    }
#pragma unroll
    for (int nt = 0; nt < 4; nt++) {
        int col = wn * 32 + nt * 8 + 2 * c;
        float bx = sb0[col], by = sb0[col + 1];
#pragma unroll
        for (int mt = 0; mt < 2; mt++) {
            int r0 = wm * 32 + mt * 16 + g;
            __half2 v0 = __floats2half2_rn(fmaxf(acc[mt][nt][0] + bx, 0.f),
                                           fmaxf(acc[mt][nt][1] + by, 0.f));
            *(__half2*)&sA[r0 * HP + col] = v0;
            __half2 v1 = __floats2half2_rn(fmaxf(acc[mt][nt][2] + bx, 0.f),
                                           fmaxf(acc[mt][nt][3] + by, 0.f));
            *(__half2*)&sA[(r0 + 8) * HP + col] = v1;
        }
    }
    __syncthreads();   // layer-1 reads of sEA/sB0 (buf0) done; h1 visible

    // prefetch B chunk 0 into buf0 (overlaps layer 2)
#pragma unroll
    for (int i = 0; i < 2; i++) {
        int row = r + i * 32;
        unsigned sa = (unsigned)__cvta_generic_to_shared((char*)sU + row * 144 + x * 16);
        cp_async16(sa, g_Bt + (size_t)row * 64 + x * 8);
    }
    cp_commit();

    // ---- MLP layer 2: [128,64] @ [64,64], A = h1 in sA, B = sB1 (buf1) ----
#pragma unroll
    for (int mt = 0; mt < 2; mt++)
#pragma unroll
        for (int nt = 0; nt < 4; nt++)
#pragma unroll
            for (int q = 0; q < 4; q++) acc[mt][nt][q] = 0.f;

#pragma unroll
    for (int kk = 0; kk < 4; kk++) {
        int kb = kk * 16;
        unsigned a_[2][4];
#pragma unroll
        for (int mt = 0; mt < 2; mt++) {
            int r0 = wm * 32 + mt * 16 + g;
            a_[mt][0] = *(const unsigned*)&sA[r0 * HP + kb + 2 * c];
            a_[mt][1] = *(const unsigned*)&sA[(r0 + 8) * HP + kb + 2 * c];
            a_[mt][2] = *(const unsigned*)&sA[r0 * HP + kb + 2 * c + 8];
            a_[mt][3] = *(const unsigned*)&sA[(r0 + 8) * HP + kb + 2 * c + 8];
        }
#pragma unroll
        for (int nt = 0; nt < 4; nt++) {
            int n0 = wn * 32 + nt * 8 + g;
            unsigned b0 = *(const unsigned*)&sB1[n0 * HP + kb + 2 * c];
            unsigned b1 = *(const unsigned*)&sB1[n0 * HP + kb + 2 * c + 8];
#pragma unroll
            for (int mt = 0; mt < 2; mt++) {
                asm volatile(
                    "mma.sync.aligned.m16n8k16.row.col.f32.f16.f16.f32 "
                    "{%0,%1,%2,%3}, {%4,%5,%6,%7}, {%8,%9}, {%0,%1,%2,%3};"
                    : "+f"(acc[mt][nt][0]), "+f"(acc[mt][nt][1]),
                      "+f"(acc[mt][nt][2]), "+f"(acc[mt][nt][3])
                    : "r"(a_[mt][0]), "r"(a_[mt][1]), "r"(a_[mt][2]), "r"(a_[mt][3]),
                      "r"(b0), "r"(b1));
            }
        }
    }
    __syncthreads();   // all sA (h1) + sB1 (buf1) reads done

    // epilogue: e2 = bias + relu -> sA (GEMM A tile)
#pragma unroll
    for (int nt = 0; nt < 4; nt++) {
        int col = wn * 32 + nt * 8 + 2 * c;
        float bx = sb1[col], by = sb1[col + 1];
#pragma unroll
        for (int mt = 0; mt < 2; mt++) {
            int r0 = wm * 32 + mt * 16 + g;
            __half2 v0 = __floats2half2_rn(fmaxf(acc[mt][nt][0] + bx, 0.f),
                                           fmaxf(acc[mt][nt][1] + by, 0.f));
            *(__half2*)&sA[r0 * HP + col] = v0;
            __half2 v1 = __floats2half2_rn(fmaxf(acc[mt][nt][2] + bx, 0.f),
                                           fmaxf(acc[mt][nt][3] + by, 0.f));
            *(__half2*)&sA[(r0 + 8) * HP + col] = v1;
        }
    }

    // ---- GEMM phase: 16 chunks of 64 cols ----
    int sel = lane >> 3;
    int l7 = lane & 7;

    unsigned aAddr[4][2];
#pragma unroll
    for (int kk = 0; kk < 4; kk++) {
#pragma unroll
        for (int mt = 0; mt < 2; mt++) {
            int rowa = wm * 32 + mt * 16 + (sel & 1) * 8 + l7;
            int cola = kk * 16 + (sel >> 1) * 8;
            aAddr[kk][mt] = (unsigned)__cvta_generic_to_shared(&sA[rowa * HPITCH + cola]);
        }
    }

#pragma unroll 1
    for (int ch = 0; ch < 16; ch++) {
        cp_wait_all();
        __syncthreads();   // B[ch&1] ready; e2 visible (ch=0); prev iter done

        if (ch < 15) {
            int bnn = (ch + 1) * 64;
            char* dstbuf = (char*)sU + ((ch + 1) & 1) * (64 * 144);
#pragma unroll
            for (int i = 0; i < 2; i++) {
                int row = r + i * 32;
                unsigned sa = (unsigned)__cvta_generic_to_shared(dstbuf + row * 144 + x * 16);
                cp_async16(sa, g_Bt + (size_t)(bnn + row) * 64 + x * 8);
            }
        }
        cp_commit();

        const __half* sBc = sU + (ch & 1) * (64 * HPITCH);
        int bn = ch * 64;

        float acc2[2][4][4];
#pragma unroll
        for (int mt = 0; mt < 2; mt++)
#pragma unroll
            for (int nt = 0; nt < 4; nt++)
#pragma unroll
                for (int q = 0; q < 4; q++) acc2[mt][nt][q] = 0.f;

#pragma unroll
        for (int kk = 0; kk < 4; kk++) {
            int kb = kk * 16;
            unsigned a_[2][4];
#pragma unroll
            for (int mt = 0; mt < 2; mt++)
                ldsm_x4(a_[mt][0], a_[mt][1], a_[mt][2], a_[mt][3], aAddr[kk][mt]);

            unsigned b_[4][2];
            {
                int rowb0 = wn * 32 + ((sel < 2) ? 0 : 8) + l7;
                int colb  = kb + (sel & 1) * 8;
                unsigned a0 = (unsigned)__cvta_generic_to_shared(&sBc[rowb0 * HPITCH + colb]);
                ldsm_x4(b_[0][0], b_[0][1], b_[1][0], b_[1][1], a0);
                int rowb1 = wn * 32 + ((sel < 2) ? 16 : 24) + l7;
                unsigned a1 = (unsigned)__cvta_generic_to_shared(&sBc[rowb1 * HPITCH + colb]);
                ldsm_x4(b_[2][0], b_[2][1], b_[3][0], b_[3][1], a1);
            }
#pragma unroll
            for (int mt = 0; mt < 2; mt++)
#pragma unroll
                for (int nt = 0; nt < 4; nt++) {
                    asm volatile(
                        "mma.sync.aligned.m16n8k16.row.col.f32.f16.f16.f32 "
                        "{%0,%1,%2,%3}, {%4,%5,%6,%7}, {%8,%9}, {%0,%1,%2,%3};"
                        : "+f"(acc2[mt][nt][0]), "+f"(acc2[mt][nt][1]),
                          "+f"(acc2[mt][nt][2]), "+f"(acc2[mt][nt][3])
                        : "r"(a_[mt][0]), "r"(a_[mt][1]), "r"(a_[mt][2]), "r"(a_[mt][3]),
                          "r"(b_[nt][0]), "r"(b_[nt][1]));
                }
        }

        // direct permuted store
        {
            int hcol = (bn + wn * 32);
            float bb[4][2];
#pragma unroll
            for (int nt = 0; nt < 4; nt++) {
                int col = hcol + nt * 8 + 2 * c;
                bb[nt][0] = sbias[col];
                bb[nt][1] = sbias[col + 1];
            }
#pragma unroll
            for (int mt = 0; mt < 2; mt++) {
#pragma unroll
                for (int q = 0; q < 2; q++) {
                    int er = bm + wm * 32 + mt * 16 + q * 8 + g;
                    if (er < E) {
                        __half2 v[4];
#pragma unroll
                        for (int nt = 0; nt < 4; nt++)
                            v[nt] = __floats2half2_rn(acc2[mt][nt][2 * q] + bb[nt][0],
                                                      acc2[mt][nt][2 * q + 1] + bb[nt][1]);
                        uint4 pk;
                        pk.x = *(unsigned*)&v[0]; pk.y = *(unsigned*)&v[1];
                        pk.z = *(unsigned*)&v[2]; pk.w = *(unsigned*)&v[3];
                        *(uint4*)(g_Wh + (size_t)er * 1024 + hcol + c * 8) = pk;
                    }
                }
            }
        }
    }
}

// ---------------------------------------------------------------------------
// message passing (unchanged)
// ---------------------------------------------------------------------------
__global__ __launch_bounds__(256) void k_msg(const int* __restrict__ ei, int selIn, int E) {
    int gw = (blockIdx.x * blockDim.x + threadIdx.x) >> 5;
    int lane = threadIdx.x & 31;
    if (gw >= E) return;
    const float* __restrict__ h = (selIn == 0) ? g_h0 : (selIn == 1) ? g_ha : g_hb;

    int2 sd = ((const int2*)ei)[gw];
    int src = sd.x, dst = sd.y;
    float hval = h[(size_t)src * 32 + lane];

    const uint4* __restrict__ W16 = (const uint4*)(g_Wh + (size_t)gw * 1024);
    float acc[8];
#pragma unroll
    for (int j = 0; j < 8; j++) acc[j] = 0.f;

#pragma unroll
    for (int i = 0; i < 4; i++) {
        uint4 w = W16[lane + 32 * i];
        float hs = __shfl_sync(0xffffffffu, hval, (lane >> 2) + 8 * i);
        const __half2* h2 = (const __half2*)&w;
#pragma unroll
        for (int j = 0; j < 4; j++) {
            float2 f = __half22float2(h2[j]);
            acc[2 * j]     += hs * f.x;
            acc[2 * j + 1] += hs * f.y;
        }
    }
#pragma unroll
    for (int m = 4; m <= 16; m <<= 1) {
#pragma unroll
        for (int j = 0; j < 8; j++)
            acc[j] += __shfl_xor_sync(0xffffffffu, acc[j], m);
    }
    int k = lane >> 2;
    float v = acc[0];
    if (k == 1) v = acc[1];
    if (k == 2) v = acc[2];
    if (k == 3) v = acc[3];
    if (k == 4) v = acc[4];
    if (k == 5) v = acc[5];
    if (k == 6) v = acc[6];
    if (k == 7) v = acc[7];
    int o = ((k >> 1) << 3) + ((lane & 3) << 1) + (k & 1);
    atomicAdd(&g_agg[(size_t)dst * 32 + o], v);
}

// ---------------------------------------------------------------------------
// node update (unchanged wide version)
// ---------------------------------------------------------------------------
__global__ __launch_bounds__(1024) void k_update(
    int selIn, int selOut, const float* __restrict__ root,
    const float* __restrict__ bias, int N) {
    __shared__ float sroot[32 * 32];
    __shared__ float sb[32];
    int tid = threadIdx.x;
    if (tid < 1024) sroot[tid] = root[tid];
    if (tid < 32) sb[tid] = bias[tid];
    __syncthreads();

    int lane = tid & 31, w = tid >> 5;
    int n = blockIdx.x * 32 + w;
    if (n >= N) return;
    const float* __restrict__ hin = (selIn == 0) ? g_h0 : (selIn == 1) ? g_ha : g_hb;
    float* __restrict__ hout = (selOut == 1) ? g_ha : g_hb;

    float hv = hin[(size_t)n * 32 + lane];
    float acc = sb[lane] + g_agg[(size_t)n * 32 + lane];
    g_agg[(size_t)n * 32 + lane] = 0.0f;
#pragma unroll
    for (int k = 0; k < 32; k++)
        acc += __shfl_sync(0xffffffffu, hv, k) * sroot[k * 32 + lane];
    hout[(size_t)n * 32 + lane] = acc;
}

// ---------------------------------------------------------------------------
// readout (unchanged wide version)
// ---------------------------------------------------------------------------
__global__ __launch_bounds__(1024) void k_readout(
    const float* __restrict__ Wi0, const float* __restrict__ bi0,
    const float* __restrict__ Wi1, const float* __restrict__ bi1,
    const float* __restrict__ Wj0, const float* __restrict__ bj0,
    const float* __restrict__ Wj1, const float* __restrict__ bj1,
    float* __restrict__ out, int N) {
    __shared__ float sW[64 * 128];
    __shared__ float sv1[128];
    __shared__ float sblock;
    int tid = threadIdx.x, lane = tid & 31, w = tid >> 5;
    int n = blockIdx.x * 32 + w;
    bool active = (n < N);

    for (int i = tid; i < 64 * 128; i += 1024) sW[i] = Wi0[i];
    if (tid < 128) sv1[tid] = Wi1[tid];
    if (tid == 0) sblock = 0.f;
    __syncthreads();

    float za = 0.f, zb = 0.f;
    if (active) {
        za = g_ha[(size_t)n * 32 + lane];
        zb = g_h0[(size_t)n * 32 + lane];
    }

    float a0 = bi0[lane], a1 = bi0[lane + 32], a2 = bi0[lane + 64], a3 = bi0[lane + 96];
#pragma unroll
    for (int k = 0; k < 32; k++) {
        float zk = __shfl_sync(0xffffffffu, za, k);
        a0 += zk * sW[k * 128 + lane];
        a1 += zk * sW[k * 128 + lane + 32];
        a2 += zk * sW[k * 128 + lane + 64];
        a3 += zk * sW[k * 128 + lane + 96];
    }
#pragma unroll
    for (int k = 0; k < 32; k++) {
        float zk = __shfl_sync(0xffffffffu, zb, k);
        a0 += zk * sW[(k + 32) * 128 + lane];
        a1 += zk * sW[(k + 32) * 128 + lane + 32];
        a2 += zk * sW[(k + 32) * 128 + lane + 64];
        a3 += zk * sW[(k + 32) * 128 + lane + 96];
    }
    a0 = fmaxf(a0, 0.f); a1 = fmaxf(a1, 0.f); a2 = fmaxf(a2, 0.f); a3 = fmaxf(a3, 0.f);
    float gp = a0 * sv1[lane] + a1 * sv1[lane + 32] + a2 * sv1[lane + 64] + a3 * sv1[lane + 96];
#pragma unroll
    for (int s = 16; s > 0; s >>= 1) gp += __shfl_xor_sync(0xffffffffu, gp, s);
    float gate = 1.0f / (1.0f + expf(-(gp + bi1[0])));

    __syncthreads();
    for (int i = tid; i < 32 * 128; i += 1024) sW[i] = Wj0[i];
    if (tid < 128) sv1[tid] = Wj1[tid];
    __syncthreads();

    float b0 = bj0[lane], b1 = bj0[lane + 32], b2 = bj0[lane + 64], b3 = bj0[lane + 96];
#pragma unroll
    for (int k = 0; k < 32; k++) {
        float zk = __shfl_sync(0xffffffffu, za, k);
        b0 += zk * sW[k * 128 + lane];
        b1 += zk * sW[k * 128 + lane + 32];
        b2 += zk * sW[k * 128 + lane + 64];
        b3 += zk * sW[k * 128 + lane + 96];
    }
    b0 = fmaxf(b0, 0.f); b1 = fmaxf(b1, 0.f); b2 = fmaxf(b2, 0.f); b3 = fmaxf(b3, 0.f);
    float vp = b0 * sv1[lane] + b1 * sv1[lane + 32] + b2 * sv1[lane + 64] + b3 * sv1[lane + 96];
#pragma unroll
    for (int s = 16; s > 0; s >>= 1) vp += __shfl_xor_sync(0xffffffffu, vp, s);
    float val = vp + bj1[0];

    if (active && lane == 0) atomicAdd(&sblock, gate * val);
    __syncthreads();
    if (tid == 0) atomicAdd(out, sblock);
}

// ---------------------------------------------------------------------------
extern "C" void kernel_launch(void* const* d_in, const int* in_sizes, int n_in,
                              void* d_out, int out_size) {
    const float* x   = (const float*)d_in[0];
    const int*   ei  = (const int*)d_in[1];
    const float* ea  = (const float*)d_in[2];
    const float* Wm0 = (const float*)d_in[3];  const float* bm0 = (const float*)d_in[4];
    const float* Wm1 = (const float*)d_in[5];  const float* bm1 = (const float*)d_in[6];
    const float* Wm2 = (const float*)d_in[7];  const float* bm2 = (const float*)d_in[8];
    const float* root= (const float*)d_in[9];  const float* bias= (const float*)d_in[10];
    const float* Wi0 = (const float*)d_in[11]; const float* bi0 = (const float*)d_in[12];
    const float* Wi1 = (const float*)d_in[13]; const float* bi1 = (const float*)d_in[14];
    const float* Wj0 = (const float*)d_in[15]; const float* bj0 = (const float*)d_in[16];
    const float* Wj1 = (const float*)d_in[17]; const float* bj1 = (const float*)d_in[18];
    int N = in_sizes[0] / 16;
    int E = in_sizes[2] / 16;
    float* out = (float*)d_out;

    k_init<<<(N * 32 + 255) / 256, 256>>>(x, N, out, out_size);
    k_convB<<<(64 * 1024 + 255) / 256, 256>>>(Wm2, Wm0, Wm1);

    k_fused<<<(E + 127) / 128, 256>>>(ea, bm0, bm1, bm2, E);

    int msgBlocks = (E + 7) / 8;
    int nodeBlocks = (N + 31) / 32;
    // iter 1: h0 -> ha
    k_msg<<<msgBlocks, 256>>>(ei, 0, E);
    k_update<<<nodeBlocks, 1024>>>(0, 1, root, bias, N);
    // iter 2: ha -> hb
    k_msg<<<msgBlocks, 256>>>(ei, 1, E);
    k_update<<<nodeBlocks, 1024>>>(1, 2, root, bias, N);
    // iter 3: hb -> ha
    k_msg<<<msgBlocks, 256>>>(ei, 2, E);
    k_update<<<nodeBlocks, 1024>>>(2, 1, root, bias, N);

    k_readout<<<nodeBlocks, 1024>>>(Wi0, bi0, Wi1, bi1, Wj0, bj0, Wj1, bj1, out, N);
}